// round 10
// baseline (speedup 1.0000x reference)
#include <cuda_runtime.h>
#include <math.h>

#define NN   100000
#define EE   1600000
#define HIDD 64
#define BM   128
#define BKP  68          // 67 padded to 68 (zero column)
#define TPE  128         // threads per edge block (8x8 per-thread tiles)
#define TPB  256         // threads per node block
#define NPAD 100096      // 782 * 128
#define GRID_E 444       // 3 CTAs/SM for edge kernels
#define GRID_N 296       // 2 CTAs/SM for node kernels

typedef unsigned long long u64;

// ---------------- scratch (device globals; no allocations allowed) ----------
__device__ float  g_h1[(size_t)EE * HIDD];     // pre-BN edge activations (409.6 MB)
__device__ float  g_agg[(size_t)NN * HIDD];    // scatter-sum accumulator
__device__ float  g_o1[(size_t)NPAD * HIDD];   // pre-BN node activations
__device__ float  g_cnt[NN];
__device__ double g_sum_e[HIDD], g_sq_e[HIDD], g_sum_n[HIDD], g_sq_n[HIDD];
__device__ int    g_mode64;                    // 1 if edge_index is int64

// ---------------- packed f32x2 helpers (sm_100+) -----------------------------
__device__ __forceinline__ u64 bcast2(float a) {
    u64 r;
    asm("mov.b64 %0, {%1, %1};" : "=l"(r) : "f"(a));
    return r;
}
__device__ __forceinline__ u64 packf2(float lo, float hi) {
    u64 r;
    asm("mov.b64 %0, {%1, %2};" : "=l"(r) : "f"(lo), "f"(hi));
    return r;
}
__device__ __forceinline__ void unpackf2(u64 v, float& lo, float& hi) {
    asm("mov.b64 {%0, %1}, %2;" : "=f"(lo), "=f"(hi) : "l"(v));
}
__device__ __forceinline__ void fmaf2(u64& acc, u64 a, u64 b) {
    asm("fma.rn.f32x2 %0, %1, %2, %0;" : "+l"(acc) : "l"(a), "l"(b));
}
__device__ __forceinline__ void red4(float* p, float a, float b, float c, float d) {
    asm volatile("red.global.add.v4.f32 [%0], {%1, %2, %3, %4};"
                 :: "l"(p), "f"(a), "f"(b), "f"(c), "f"(d) : "memory");
}

// 8-col k-step: one A scalar against 8 weight cols (4 u64)
__device__ __forceinline__ void fma8(u64* acc4, u64 a,
                                     const ulonglong2 wa, const ulonglong2 wb) {
    fmaf2(acc4[0], a, wa.x); fmaf2(acc4[1], a, wa.y);
    fmaf2(acc4[2], a, wb.x); fmaf2(acc4[3], a, wb.y);
}

// legacy 4-col k-step (node kernels)
__device__ __forceinline__ void kstep(const float4 av,
                                      const ulonglong2 w0, const ulonglong2 w1,
                                      const ulonglong2 w2, const ulonglong2 w3,
                                      u64& a01, u64& a23) {
    u64 ax = bcast2(av.x), ay = bcast2(av.y);
    u64 az = bcast2(av.z), aw = bcast2(av.w);
    fmaf2(a01, ax, w0.x); fmaf2(a23, ax, w0.y);
    fmaf2(a01, ay, w1.x); fmaf2(a23, ay, w1.y);
    fmaf2(a01, az, w2.x); fmaf2(a23, az, w2.y);
    fmaf2(a01, aw, w3.x); fmaf2(a23, aw, w3.y);
}

// ---------------- init: detect index dtype + zero stats ---------------------
__global__ void k_init(const void* __restrict__ ei) {
    __shared__ int flag;
    int t = threadIdx.x;
    if (t == 0) flag = 0;
    __syncthreads();
    const int* w = (const int*)ei;
    for (int i = t; i < 2048; i += TPB)
        if (w[2 * i + 1] != 0) flag = 1;
    __syncthreads();
    if (t == 0) g_mode64 = (flag == 0) ? 1 : 0;
    if (t < HIDD) {
        g_sum_e[t] = 0.0; g_sq_e[t] = 0.0;
        g_sum_n[t] = 0.0; g_sq_n[t] = 0.0;
    }
}

// ---------------- zero scatter accumulators ----------------------------------
__global__ void k_zero() {
    size_t idx = (size_t)blockIdx.x * blockDim.x + threadIdx.x;
    size_t stride = (size_t)gridDim.x * blockDim.x;
    float4* a4 = (float4*)g_agg;
    size_t n4 = (size_t)NN * HIDD / 4;
    for (size_t i = idx; i < n4; i += stride) a4[i] = make_float4(0.f, 0.f, 0.f, 0.f);
    for (size_t i = idx; i < NN; i += stride) g_cnt[i] = 0.f;
}

// ---------------- edge pass 1: h1 = [x[row]||ea] @ w1 + b1, stats ------------
// 8 rows x 8 cols per thread; rows m = ty + 16*r (conflict-free A reads)
__global__ void __launch_bounds__(TPE, 3) k_edge1(
    const float* __restrict__ x, const void* __restrict__ ei,
    const float* __restrict__ ea, const float* __restrict__ w1,
    const float* __restrict__ b1)
{
    extern __shared__ float smem[];
    float* As   = smem;                 // BM * BKP (stride 17 float4)
    float* Ws   = As + BM * BKP;        // BKP * 64
    float* ssum = Ws + BKP * 64;        // 64
    float* ssq  = ssum + 64;            // 64
    const int t  = threadIdx.x;
    const int tx = t & 7, ty = t >> 3;
    const bool m64 = (g_mode64 != 0);
    const int* ei32 = (const int*)ei;
    const long long* ei64 = (const long long*)ei;

    // permuted weights: rows 0..63 <- w1[3+k], 64..66 <- w1[k-64], 67 <- 0
    for (int i = t; i < BKP * 64; i += TPE) {
        int k = i >> 6, c = i & 63;
        float v = 0.f;
        if (k < 64)      v = w1[(k + 3) * 64 + c];
        else if (k < 67) v = w1[(k - 64) * 64 + c];
        Ws[i] = v;
    }
    if (t < 64) { ssum[t] = 0.f; ssq[t] = 0.f; }

    const float4 bA = ((const float4*)b1)[2 * tx];
    const float4 bB = ((const float4*)b1)[2 * tx + 1];
    const u64 bias0 = packf2(bA.x, bA.y), bias1 = packf2(bA.z, bA.w);
    const u64 bias2 = packf2(bB.x, bB.y), bias3 = packf2(bB.z, bB.w);
    float lsum[8], lsq[8];
    #pragma unroll
    for (int c = 0; c < 8; ++c) { lsum[c] = 0.f; lsq[c] = 0.f; }

    const float4* ea4 = (const float4*)ea;
    float4* As4w = (float4*)As;
    const int ntiles = EE / BM;

    for (int tile = blockIdx.x; tile < ntiles; tile += gridDim.x) {
        const int e0 = tile * BM;
        __syncthreads();
        // stage edge_attr: 16 float4 per thread (s&15 == t&15 since TPE=128)
        #pragma unroll
        for (int i = 0; i < 16; ++i) {
            int s = t + i * TPE;
            As4w[(s >> 4) * 17 + (s & 15)] = ea4[(size_t)e0 * 16 + s];
        }
        // gather x for this thread's staging row
        {
            int e = e0 + t;
            int r = m64 ? (int)ei64[e] : ei32[e];
            const float* xp = x + (size_t)r * 3;
            float* rowp = As + t * BKP + 64;
            rowp[0] = xp[0]; rowp[1] = xp[1]; rowp[2] = xp[2]; rowp[3] = 0.f;
        }
        __syncthreads();

        u64 acc[8][4];
        #pragma unroll
        for (int r = 0; r < 8; ++r) {
            acc[r][0] = bias0; acc[r][1] = bias1;
            acc[r][2] = bias2; acc[r][3] = bias3;
        }
        const float4* As4 = (const float4*)As;
        const ulonglong2* Ws2 = (const ulonglong2*)Ws;
        #pragma unroll
        for (int kk = 0; kk < 17; ++kk) {
            ulonglong2 w0a = Ws2[(4 * kk + 0) * 16 + 2 * tx];
            ulonglong2 w0b = Ws2[(4 * kk + 0) * 16 + 2 * tx + 1];
            ulonglong2 w1a = Ws2[(4 * kk + 1) * 16 + 2 * tx];
            ulonglong2 w1b = Ws2[(4 * kk + 1) * 16 + 2 * tx + 1];
            ulonglong2 w2a = Ws2[(4 * kk + 2) * 16 + 2 * tx];
            ulonglong2 w2b = Ws2[(4 * kk + 2) * 16 + 2 * tx + 1];
            ulonglong2 w3a = Ws2[(4 * kk + 3) * 16 + 2 * tx];
            ulonglong2 w3b = Ws2[(4 * kk + 3) * 16 + 2 * tx + 1];
            #pragma unroll
            for (int r = 0; r < 8; ++r) {
                float4 av = As4[(ty + 16 * r) * 17 + kk];
                fma8(acc[r], bcast2(av.x), w0a, w0b);
                fma8(acc[r], bcast2(av.y), w1a, w1b);
                fma8(acc[r], bcast2(av.z), w2a, w2b);
                fma8(acc[r], bcast2(av.w), w3a, w3b);
            }
        }
        float4* o4 = ((float4*)g_h1) + (size_t)e0 * 16;
        #pragma unroll
        for (int r = 0; r < 8; ++r) {
            int m = ty + 16 * r;
            float v0, v1, v2, v3, v4, v5, v6, v7;
            unpackf2(acc[r][0], v0, v1); unpackf2(acc[r][1], v2, v3);
            unpackf2(acc[r][2], v4, v5); unpackf2(acc[r][3], v6, v7);
            o4[m * 16 + 2 * tx]     = make_float4(v0, v1, v2, v3);
            o4[m * 16 + 2 * tx + 1] = make_float4(v4, v5, v6, v7);
            lsum[0] += v0; lsum[1] += v1; lsum[2] += v2; lsum[3] += v3;
            lsum[4] += v4; lsum[5] += v5; lsum[6] += v6; lsum[7] += v7;
            lsq[0] += v0 * v0; lsq[1] += v1 * v1; lsq[2] += v2 * v2; lsq[3] += v3 * v3;
            lsq[4] += v4 * v4; lsq[5] += v5 * v5; lsq[6] += v6 * v6; lsq[7] += v7 * v7;
        }
    }
    __syncthreads();
    #pragma unroll
    for (int c = 0; c < 8; ++c) {
        atomicAdd(&ssum[tx * 8 + c], lsum[c]);
        atomicAdd(&ssq[tx * 8 + c],  lsq[c]);
    }
    __syncthreads();
    if (t < 64) {
        atomicAdd(&g_sum_e[t], (double)ssum[t]);
        atomicAdd(&g_sq_e[t],  (double)ssq[t]);
    }
}

// ---------------- edge pass 2: relu(bn(h1)) @ w2 + b2, scatter ---------------
__global__ void __launch_bounds__(TPE, 3) k_edge2(
    const void* __restrict__ ei, const float* __restrict__ w2,
    const float* __restrict__ b2, const float* __restrict__ g1,
    const float* __restrict__ be1)
{
    extern __shared__ float smem[];
    float* As = smem;                // BM * 68 (stride 17 float4; cols 64..67 unused)
    float* Ws = As + BM * BKP;       // 4096
    float* sc = Ws + 4096;           // 64
    float* bi = sc + 64;             // 64
    int* cidx = (int*)(bi + 64);     // BM
    const int t  = threadIdx.x;
    const int tx = t & 7, ty = t >> 3;
    const bool m64 = (g_mode64 != 0);
    const int* ei32 = (const int*)ei;
    const long long* ei64 = (const long long*)ei;

    for (int i = t; i < 4096; i += TPE) Ws[i] = w2[i];
    if (t < 64) {
        double m = g_sum_e[t] * (1.0 / (double)EE);
        double v = g_sq_e[t] * (1.0 / (double)EE) - m * m;
        double s = (double)g1[t] / sqrt(v + 1e-5);
        sc[t] = (float)s;
        bi[t] = be1[t] - (float)(m * s);
    }
    __syncthreads();
    const int c4 = t & 15;                       // staging col-group (s&15 == t&15)
    const float4 sc4 = ((const float4*)sc)[c4];
    const float4 bi4 = ((const float4*)bi)[c4];
    const float4 bA = ((const float4*)b2)[2 * tx];
    const float4 bB = ((const float4*)b2)[2 * tx + 1];
    const u64 bias0 = packf2(bA.x, bA.y), bias1 = packf2(bA.z, bA.w);
    const u64 bias2 = packf2(bB.x, bB.y), bias3 = packf2(bB.z, bB.w);

    const float4* h14 = (const float4*)g_h1;
    float4* As4w = (float4*)As;
    const int ntiles = EE / BM;

    for (int tile = blockIdx.x; tile < ntiles; tile += gridDim.x) {
        const int e0 = tile * BM;
        __syncthreads();
        #pragma unroll
        for (int i = 0; i < 16; ++i) {
            int s = t + i * TPE;
            float4 v = h14[(size_t)e0 * 16 + s];
            v.x = fmaxf(fmaf(v.x, sc4.x, bi4.x), 0.f);
            v.y = fmaxf(fmaf(v.y, sc4.y, bi4.y), 0.f);
            v.z = fmaxf(fmaf(v.z, sc4.z, bi4.z), 0.f);
            v.w = fmaxf(fmaf(v.w, sc4.w, bi4.w), 0.f);
            As4w[(s >> 4) * 17 + (s & 15)] = v;
        }
        {
            int e = e0 + t;
            int d = m64 ? (int)ei64[(size_t)EE + e] : ei32[(size_t)EE + e];
            cidx[t] = d;
            atomicAdd(&g_cnt[d], 1.0f);
        }
        __syncthreads();

        u64 acc[8][4];
        #pragma unroll
        for (int r = 0; r < 8; ++r) {
            acc[r][0] = bias0; acc[r][1] = bias1;
            acc[r][2] = bias2; acc[r][3] = bias3;
        }
        const float4* As4 = (const float4*)As;
        const ulonglong2* Ws2 = (const ulonglong2*)Ws;
        #pragma unroll
        for (int kk = 0; kk < 16; ++kk) {
            ulonglong2 w0a = Ws2[(4 * kk + 0) * 16 + 2 * tx];
            ulonglong2 w0b = Ws2[(4 * kk + 0) * 16 + 2 * tx + 1];
            ulonglong2 w1a = Ws2[(4 * kk + 1) * 16 + 2 * tx];
            ulonglong2 w1b = Ws2[(4 * kk + 1) * 16 + 2 * tx + 1];
            ulonglong2 w2a = Ws2[(4 * kk + 2) * 16 + 2 * tx];
            ulonglong2 w2b = Ws2[(4 * kk + 2) * 16 + 2 * tx + 1];
            ulonglong2 w3a = Ws2[(4 * kk + 3) * 16 + 2 * tx];
            ulonglong2 w3b = Ws2[(4 * kk + 3) * 16 + 2 * tx + 1];
            #pragma unroll
            for (int r = 0; r < 8; ++r) {
                float4 av = As4[(ty + 16 * r) * 17 + kk];
                fma8(acc[r], bcast2(av.x), w0a, w0b);
                fma8(acc[r], bcast2(av.y), w1a, w1b);
                fma8(acc[r], bcast2(av.z), w2a, w2b);
                fma8(acc[r], bcast2(av.w), w3a, w3b);
            }
        }
        #pragma unroll
        for (int r = 0; r < 8; ++r) {
            int m = ty + 16 * r;
            float v0, v1, v2, v3, v4, v5, v6, v7;
            unpackf2(acc[r][0], v0, v1); unpackf2(acc[r][1], v2, v3);
            unpackf2(acc[r][2], v4, v5); unpackf2(acc[r][3], v6, v7);
            float* p = g_agg + (size_t)cidx[m] * 64 + tx * 8;
            red4(p,     v0, v1, v2, v3);
            red4(p + 4, v4, v5, v6, v7);
        }
    }
}

// ---------------- node pass 1: o1 = [x||agg/cnt] @ w3 + b3, stats ------------
__global__ void __launch_bounds__(TPB, 2) k_node1(
    const float* __restrict__ x, const float* __restrict__ w3,
    const float* __restrict__ b3)
{
    extern __shared__ float smem[];
    float* As   = smem;                 // BM * BKP
    float* Ws   = As + BM * BKP;        // BKP * 64
    float* ssum = Ws + BKP * 64;        // 64
    float* ssq  = ssum + 64;            // 64
    float* rcnt = ssq + 64;             // BM
    const int t  = threadIdx.x;
    const int tx = t & 15, ty = t >> 4;

    for (int i = t; i < BKP * 64; i += TPB) {
        int k = i >> 6, c = i & 63;
        float v = 0.f;
        if (k < 64)      v = w3[(k + 3) * 64 + c];
        else if (k < 67) v = w3[(k - 64) * 64 + c];
        Ws[i] = v;
    }
    if (t < 64) { ssum[t] = 0.f; ssq[t] = 0.f; }

    const float4 bias = ((const float4*)b3)[tx];
    const u64 bias01 = packf2(bias.x, bias.y);
    const u64 bias23 = packf2(bias.z, bias.w);
    float lsum[4] = {0.f, 0.f, 0.f, 0.f};
    float lsq[4]  = {0.f, 0.f, 0.f, 0.f};

    const float4* agg4 = (const float4*)g_agg;
    float4* As4w = (float4*)As;
    const int ntiles = NPAD / BM;
    for (int tile = blockIdx.x; tile < ntiles; tile += gridDim.x) {
        const int m0 = tile * BM;
        __syncthreads();
        if (t < BM) {
            int m = m0 + t;
            float c = (m < NN) ? g_cnt[m] : 0.f;
            rcnt[t] = 1.f / fmaxf(c, 1.f);
            float* rowp = As + t * BKP + 64;
            if (m < NN) {
                const float* xp = x + (size_t)m * 3;
                rowp[0] = xp[0]; rowp[1] = xp[1]; rowp[2] = xp[2];
            } else { rowp[0] = 0.f; rowp[1] = 0.f; rowp[2] = 0.f; }
            rowp[3] = 0.f;
        }
        __syncthreads();
        #pragma unroll
        for (int i = 0; i < 8; ++i) {
            int s = t + i * TPB;
            int m = s >> 4, q = s & 15;
            int gm = m0 + m;
            float4 v = make_float4(0.f, 0.f, 0.f, 0.f);
            if (gm < NN) v = agg4[(size_t)gm * 16 + q];
            float rc = rcnt[m];
            v.x *= rc; v.y *= rc; v.z *= rc; v.w *= rc;
            As4w[m * 17 + q] = v;
        }
        __syncthreads();

        u64 acc[8][2];
        #pragma unroll
        for (int r = 0; r < 8; ++r) { acc[r][0] = bias01; acc[r][1] = bias23; }
        const float4* As4 = (const float4*)As;
        const ulonglong2* Ws2 = (const ulonglong2*)Ws;
        #pragma unroll
        for (int kk = 0; kk < 17; ++kk) {
            ulonglong2 w0 = Ws2[(4 * kk + 0) * 16 + tx];
            ulonglong2 w1v = Ws2[(4 * kk + 1) * 16 + tx];
            ulonglong2 w2v = Ws2[(4 * kk + 2) * 16 + tx];
            ulonglong2 w3v = Ws2[(4 * kk + 3) * 16 + tx];
            #pragma unroll
            for (int r = 0; r < 8; ++r) {
                float4 av = As4[(ty * 8 + r) * 17 + kk];
                kstep(av, w0, w1v, w2v, w3v, acc[r][0], acc[r][1]);
            }
        }
        float4* o4 = ((float4*)g_o1) + (size_t)m0 * 16;
        #pragma unroll
        for (int r = 0; r < 8; ++r) {
            int m = ty * 8 + r;
            float4 v;
            unpackf2(acc[r][0], v.x, v.y);
            unpackf2(acc[r][1], v.z, v.w);
            o4[m * 16 + tx] = v;
            if (m0 + m < NN) {
                lsum[0] += v.x; lsum[1] += v.y; lsum[2] += v.z; lsum[3] += v.w;
                lsq[0] += v.x * v.x; lsq[1] += v.y * v.y;
                lsq[2] += v.z * v.z; lsq[3] += v.w * v.w;
            }
        }
    }
    __syncthreads();
    #pragma unroll
    for (int c = 0; c < 4; ++c) {
        atomicAdd(&ssum[tx * 4 + c], lsum[c]);
        atomicAdd(&ssq[tx * 4 + c],  lsq[c]);
    }
    __syncthreads();
    if (t < 64) {
        atomicAdd(&g_sum_n[t], (double)ssum[t]);
        atomicAdd(&g_sq_n[t],  (double)ssq[t]);
    }
}

// ---------------- node pass 2: out = relu(bn(o1)) @ w4 + b4 ------------------
__global__ void __launch_bounds__(TPB, 2) k_node2(
    const float* __restrict__ w4, const float* __restrict__ b4,
    const float* __restrict__ g3, const float* __restrict__ be3,
    float* __restrict__ out)
{
    extern __shared__ float smem[];
    float* As = smem;                // BM * 64
    float* Ws = As + BM * 64;        // 4096
    float* sc = Ws + 4096;           // 64
    float* bi = sc + 64;             // 64
    const int t  = threadIdx.x;
    const int tx = t & 15, ty = t >> 4;

    for (int i = t; i < 4096; i += TPB) Ws[i] = w4[i];
    if (t < 64) {
        double m = g_sum_n[t] * (1.0 / (double)NN);
        double v = g_sq_n[t] * (1.0 / (double)NN) - m * m;
        double s = (double)g3[t] / sqrt(v + 1e-5);
        sc[t] = (float)s;
        bi[t] = be3[t] - (float)(m * s);
    }
    __syncthreads();
    const float4 sc4 = ((const float4*)sc)[tx];
    const float4 bi4 = ((const float4*)bi)[tx];
    const float4 bias = ((const float4*)b4)[tx];
    const u64 bias01 = packf2(bias.x, bias.y);
    const u64 bias23 = packf2(bias.z, bias.w);

    const float4* o14 = (const float4*)g_o1;
    float4* As4w = (float4*)As;
    float4* out4 = (float4*)out;
    const int ntiles = NPAD / BM;
    for (int tile = blockIdx.x; tile < ntiles; tile += gridDim.x) {
        const int m0 = tile * BM;
        __syncthreads();
        #pragma unroll
        for (int i = 0; i < 8; ++i) {
            int s = t + i * TPB;
            float4 v = o14[(size_t)m0 * 16 + s];
            v.x = fmaxf(fmaf(v.x, sc4.x, bi4.x), 0.f);
            v.y = fmaxf(fmaf(v.y, sc4.y, bi4.y), 0.f);
            v.z = fmaxf(fmaf(v.z, sc4.z, bi4.z), 0.f);
            v.w = fmaxf(fmaf(v.w, sc4.w, bi4.w), 0.f);
            As4w[s] = v;
        }
        __syncthreads();

        u64 acc[8][2];
        #pragma unroll
        for (int r = 0; r < 8; ++r) { acc[r][0] = bias01; acc[r][1] = bias23; }
        const float4* As4 = (const float4*)As;
        const ulonglong2* Ws2 = (const ulonglong2*)Ws;
        #pragma unroll
        for (int kk = 0; kk < 16; ++kk) {
            ulonglong2 w0 = Ws2[(4 * kk + 0) * 16 + tx];
            ulonglong2 w1v = Ws2[(4 * kk + 1) * 16 + tx];
            ulonglong2 w2v = Ws2[(4 * kk + 2) * 16 + tx];
            ulonglong2 w3v = Ws2[(4 * kk + 3) * 16 + tx];
            #pragma unroll
            for (int r = 0; r < 8; ++r) {
                float4 av = As4[(ty * 8 + r) * 16 + kk];
                kstep(av, w0, w1v, w2v, w3v, acc[r][0], acc[r][1]);
            }
        }
        #pragma unroll
        for (int r = 0; r < 8; ++r) {
            int m = ty * 8 + r;
            int gm = m0 + m;
            if (gm < NN) {
                float4 v;
                unpackf2(acc[r][0], v.x, v.y);
                unpackf2(acc[r][1], v.z, v.w);
                out4[(size_t)gm * 16 + tx] = v;
            }
        }
    }
}

// ---------------- launch ------------------------------------------------------
extern "C" void kernel_launch(void* const* d_in, const int* in_sizes, int n_in,
                              void* d_out, int out_size) {
    const float* x   = (const float*)d_in[0];
    const void*  ei  = d_in[1];
    const float* ea  = (const float*)d_in[2];
    // d_in[3] = u, d_in[4] = batch  (unused by reference)
    const float* w1  = (const float*)d_in[5];
    const float* b1  = (const float*)d_in[6];
    const float* g1  = (const float*)d_in[7];
    const float* be1 = (const float*)d_in[8];
    const float* w2  = (const float*)d_in[9];
    const float* b2  = (const float*)d_in[10];
    const float* w3  = (const float*)d_in[11];
    const float* b3  = (const float*)d_in[12];
    const float* g3  = (const float*)d_in[13];
    const float* be3 = (const float*)d_in[14];
    const float* w4  = (const float*)d_in[15];
    const float* b4  = (const float*)d_in[16];
    float* out = (float*)d_out;

    const int SM1 = (BM * BKP + BKP * 64 + 128) * 4;            // k_edge1 (52.7 KB)
    const int SM2 = (BM * BKP + 4096 + 128) * 4 + BM * 4;       // k_edge2 (52.2 KB)
    const int SM3 = (BM * BKP + BKP * 64 + 128 + BM) * 4;       // k_node1
    const int SM4 = (BM * 64 + 4096 + 128) * 4;                 // k_node2

    cudaFuncSetAttribute(k_edge1, cudaFuncAttributeMaxDynamicSharedMemorySize, SM1);
    cudaFuncSetAttribute(k_edge2, cudaFuncAttributeMaxDynamicSharedMemorySize, SM2);
    cudaFuncSetAttribute(k_node1, cudaFuncAttributeMaxDynamicSharedMemorySize, SM3);
    cudaFuncSetAttribute(k_node2, cudaFuncAttributeMaxDynamicSharedMemorySize, SM4);

    k_init<<<1, TPB>>>(ei);
    k_zero<<<512, TPB>>>();
    k_edge1<<<GRID_E, TPE, SM1>>>(x, ei, ea, w1, b1);
    k_edge2<<<GRID_E, TPE, SM2>>>(ei, w2, b2, g1, be1);
    k_node1<<<GRID_N, TPB, SM3>>>(x, w3, b3);
    k_node2<<<GRID_N, TPB, SM4>>>(w4, b4, g3, be3, out);
}

// round 12
// speedup vs baseline: 1.0952x; 1.0952x over previous
#include <cuda_runtime.h>
#include <math.h>

#define NN   100000
#define EE   1600000
#define HIDD 64
#define BM   128
#define BKP  68          // 67 padded to 68 (stride 17 float4)
#define TPB  256
#define NPAD 100096      // 782 * 128
#define GRID 296

typedef unsigned long long u64;

// ---------------- scratch (device globals; no allocations allowed) ----------
__device__ float  g_h1[(size_t)EE * HIDD];     // pre-BN edge activations (409.6 MB)
__device__ float  g_agg[(size_t)NN * HIDD];    // scatter-sum accumulator
__device__ float  g_o1[(size_t)NPAD * HIDD];   // pre-BN node activations
__device__ float  g_cnt[NN];
__device__ double g_sum_e[HIDD], g_sq_e[HIDD], g_sum_n[HIDD], g_sq_n[HIDD];
__device__ int    g_mode64;                    // 1 if edge_index is int64

// ---------------- packed f32x2 helpers (sm_100+) -----------------------------
__device__ __forceinline__ u64 bcast2(float a) {
    u64 r;
    asm("mov.b64 %0, {%1, %1};" : "=l"(r) : "f"(a));
    return r;
}
__device__ __forceinline__ u64 packf2(float lo, float hi) {
    u64 r;
    asm("mov.b64 %0, {%1, %2};" : "=l"(r) : "f"(lo), "f"(hi));
    return r;
}
__device__ __forceinline__ void unpackf2(u64 v, float& lo, float& hi) {
    asm("mov.b64 {%0, %1}, %2;" : "=f"(lo), "=f"(hi) : "l"(v));
}
__device__ __forceinline__ void fmaf2(u64& acc, u64 a, u64 b) {
    asm("fma.rn.f32x2 %0, %1, %2, %0;" : "+l"(acc) : "l"(a), "l"(b));
}
__device__ __forceinline__ void red4(float* p, float a, float b, float c, float d) {
    asm volatile("red.global.add.v4.f32 [%0], {%1, %2, %3, %4};"
                 :: "l"(p), "f"(a), "f"(b), "f"(c), "f"(d) : "memory");
}

// one packed k-step: 4 scalar A values against 4 weight rows (2 cols per u64)
__device__ __forceinline__ void kstep(const float4 av,
                                      const ulonglong2 w0, const ulonglong2 w1,
                                      const ulonglong2 w2, const ulonglong2 w3,
                                      u64& a01, u64& a23) {
    u64 ax = bcast2(av.x), ay = bcast2(av.y);
    u64 az = bcast2(av.z), aw = bcast2(av.w);
    fmaf2(a01, ax, w0.x); fmaf2(a23, ax, w0.y);
    fmaf2(a01, ay, w1.x); fmaf2(a23, ay, w1.y);
    fmaf2(a01, az, w2.x); fmaf2(a23, az, w2.y);
    fmaf2(a01, aw, w3.x); fmaf2(a23, aw, w3.y);
}

// ---------------- init: detect index dtype + zero stats ---------------------
__global__ void k_init(const void* __restrict__ ei) {
    __shared__ int flag;
    int t = threadIdx.x;
    if (t == 0) flag = 0;
    __syncthreads();
    const int* w = (const int*)ei;
    for (int i = t; i < 2048; i += TPB)
        if (w[2 * i + 1] != 0) flag = 1;
    __syncthreads();
    if (t == 0) g_mode64 = (flag == 0) ? 1 : 0;
    if (t < HIDD) {
        g_sum_e[t] = 0.0; g_sq_e[t] = 0.0;
        g_sum_n[t] = 0.0; g_sq_n[t] = 0.0;
    }
}

// ---------------- zero scatter accumulators ----------------------------------
__global__ void k_zero() {
    size_t idx = (size_t)blockIdx.x * blockDim.x + threadIdx.x;
    size_t stride = (size_t)gridDim.x * blockDim.x;
    float4* a4 = (float4*)g_agg;
    size_t n4 = (size_t)NN * HIDD / 4;
    for (size_t i = idx; i < n4; i += stride) a4[i] = make_float4(0.f, 0.f, 0.f, 0.f);
    for (size_t i = idx; i < NN; i += stride) g_cnt[i] = 0.f;
}

// ---------------- edge pass 1: h1 = [x[row]||ea] @ w1 + b1, stats ------------
// 8x4 per-thread tiles, rows m = ty + 16*r (conflict-free A reads),
// double-buffered A staging: ONE barrier per tile.
__global__ void __launch_bounds__(TPB, 2) k_edge1(
    const float* __restrict__ x, const void* __restrict__ ei,
    const float* __restrict__ ea, const float* __restrict__ w1,
    const float* __restrict__ b1)
{
    extern __shared__ float smem[];
    float* AsA  = smem;                 // BM * BKP (buffer 0)
    float* AsB  = AsA + BM * BKP;       // BM * BKP (buffer 1)
    float* Ws   = AsB + BM * BKP;       // BKP * 64
    float* ssum = Ws + BKP * 64;        // 64
    float* ssq  = ssum + 64;            // 64
    const int t  = threadIdx.x;
    const int tx = t & 15, ty = t >> 4;
    const int G  = gridDim.x;
    const bool m64 = (g_mode64 != 0);
    const int* ei32 = (const int*)ei;
    const long long* ei64 = (const long long*)ei;

    // permuted weights: rows 0..63 <- w1[3+k], 64..66 <- w1[k-64], 67 <- 0
    for (int i = t; i < BKP * 64; i += TPB) {
        int k = i >> 6, c = i & 63;
        float v = 0.f;
        if (k < 64)      v = w1[(k + 3) * 64 + c];
        else if (k < 67) v = w1[(k - 64) * 64 + c];
        Ws[i] = v;
    }
    if (t < 64) { ssum[t] = 0.f; ssq[t] = 0.f; }

    const float4 bias = ((const float4*)b1)[tx];
    const u64 bias01 = packf2(bias.x, bias.y);
    const u64 bias23 = packf2(bias.z, bias.w);
    float lsum[4] = {0.f, 0.f, 0.f, 0.f};
    float lsq[4]  = {0.f, 0.f, 0.f, 0.f};

    const float4* ea4 = (const float4*)ea;
    const int ntiles = EE / BM;

    float4 pf[8];
    float px0 = 0.f, px1 = 0.f, px2 = 0.f;
    int tile = blockIdx.x;

    // prologue: load+stage tile0 into buffer 0, then prefetch tile0+G
    if (tile < ntiles) {
        #pragma unroll
        for (int i = 0; i < 8; ++i)
            pf[i] = ea4[(size_t)tile * BM * 16 + t + i * TPB];
        if (t < BM) {
            int r = m64 ? (int)ei64[tile * BM + t] : ei32[tile * BM + t];
            const float* xp = x + (size_t)r * 3;
            px0 = xp[0]; px1 = xp[1]; px2 = xp[2];
        }
        float4* d4 = (float4*)AsA;
        #pragma unroll
        for (int i = 0; i < 8; ++i) {
            int s = t + i * TPB;
            d4[(s >> 4) * 17 + (s & 15)] = pf[i];
        }
        if (t < BM) {
            float* rp = AsA + t * BKP + 64;
            rp[0] = px0; rp[1] = px1; rp[2] = px2; rp[3] = 0.f;
        }
        int nx = tile + G;
        if (nx < ntiles) {
            #pragma unroll
            for (int i = 0; i < 8; ++i)
                pf[i] = ea4[(size_t)nx * BM * 16 + t + i * TPB];
            if (t < BM) {
                int r = m64 ? (int)ei64[nx * BM + t] : ei32[nx * BM + t];
                const float* xp = x + (size_t)r * 3;
                px0 = xp[0]; px1 = xp[1]; px2 = xp[2];
            }
        }
    }

    int idx = 0;
    for (; tile < ntiles; tile += G, idx ^= 1) {
        __syncthreads();
        const float* cur = idx ? AsB : AsA;
        const float4* As4 = (const float4*)cur;

        u64 acc[8][2];
        #pragma unroll
        for (int r = 0; r < 8; ++r) { acc[r][0] = bias01; acc[r][1] = bias23; }
        const ulonglong2* Ws2 = (const ulonglong2*)Ws;
        #pragma unroll
        for (int kk = 0; kk < 17; ++kk) {
            ulonglong2 w0 = Ws2[(4 * kk + 0) * 16 + tx];
            ulonglong2 w1v = Ws2[(4 * kk + 1) * 16 + tx];
            ulonglong2 w2v = Ws2[(4 * kk + 2) * 16 + tx];
            ulonglong2 w3v = Ws2[(4 * kk + 3) * 16 + tx];
            #pragma unroll
            for (int r = 0; r < 8; ++r) {
                float4 av = As4[(ty + 16 * r) * 17 + kk];
                kstep(av, w0, w1v, w2v, w3v, acc[r][0], acc[r][1]);
            }
        }

        // stage tile+G into the other buffer; prefetch tile+2G
        int nx = tile + G;
        if (nx < ntiles) {
            float* nb = idx ? AsA : AsB;
            float4* d4 = (float4*)nb;
            #pragma unroll
            for (int i = 0; i < 8; ++i) {
                int s = t + i * TPB;
                d4[(s >> 4) * 17 + (s & 15)] = pf[i];
            }
            if (t < BM) {
                float* rp = nb + t * BKP + 64;
                rp[0] = px0; rp[1] = px1; rp[2] = px2; rp[3] = 0.f;
            }
            int nx2 = tile + 2 * G;
            if (nx2 < ntiles) {
                #pragma unroll
                for (int i = 0; i < 8; ++i)
                    pf[i] = ea4[(size_t)nx2 * BM * 16 + t + i * TPB];
                if (t < BM) {
                    int r = m64 ? (int)ei64[nx2 * BM + t] : ei32[nx2 * BM + t];
                    const float* xp = x + (size_t)r * 3;
                    px0 = xp[0]; px1 = xp[1]; px2 = xp[2];
                }
            }
        }

        // epilogue: write h1, accumulate stats
        float4* o4 = ((float4*)g_h1) + (size_t)tile * BM * 16;
        #pragma unroll
        for (int r = 0; r < 8; ++r) {
            int m = ty + 16 * r;
            float4 v;
            unpackf2(acc[r][0], v.x, v.y);
            unpackf2(acc[r][1], v.z, v.w);
            o4[m * 16 + tx] = v;
            lsum[0] += v.x; lsum[1] += v.y; lsum[2] += v.z; lsum[3] += v.w;
            lsq[0] += v.x * v.x; lsq[1] += v.y * v.y;
            lsq[2] += v.z * v.z; lsq[3] += v.w * v.w;
        }
    }
    __syncthreads();
    #pragma unroll
    for (int c = 0; c < 4; ++c) {
        atomicAdd(&ssum[tx * 4 + c], lsum[c]);
        atomicAdd(&ssq[tx * 4 + c],  lsq[c]);
    }
    __syncthreads();
    if (t < 64) {
        atomicAdd(&g_sum_e[t], (double)ssum[t]);
        atomicAdd(&g_sq_e[t],  (double)ssq[t]);
    }
}

// ---------------- edge pass 2: relu(bn(h1)) @ w2 + b2, scatter ---------------
__global__ void __launch_bounds__(TPB, 2) k_edge2(
    const void* __restrict__ ei, const float* __restrict__ w2,
    const float* __restrict__ b2, const float* __restrict__ g1,
    const float* __restrict__ be1)
{
    extern __shared__ float smem[];
    float* AsA = smem;               // BM * BKP (stride 17 f4; cols 64..67 unused)
    float* AsB = AsA + BM * BKP;
    float* Ws  = AsB + BM * BKP;     // 4096
    float* sc  = Ws + 4096;          // 64
    float* bi  = sc + 64;            // 64
    int* cidx0 = (int*)(bi + 64);    // BM
    int* cidx1 = cidx0 + BM;         // BM
    const int t  = threadIdx.x;
    const int tx = t & 15, ty = t >> 4;
    const int G  = gridDim.x;
    const bool m64 = (g_mode64 != 0);
    const int* ei32 = (const int*)ei;
    const long long* ei64 = (const long long*)ei;

    for (int i = t; i < 4096; i += TPB) Ws[i] = w2[i];
    if (t < 64) {
        double m = g_sum_e[t] * (1.0 / (double)EE);
        double v = g_sq_e[t] * (1.0 / (double)EE) - m * m;
        double s = (double)g1[t] / sqrt(v + 1e-5);
        sc[t] = (float)s;
        bi[t] = be1[t] - (float)(m * s);
    }
    __syncthreads();                 // sc/bi visible before staging uses them
    const float4 sc4 = ((const float4*)sc)[tx];   // s&15 == tx for stride-256 loads
    const float4 bi4 = ((const float4*)bi)[tx];
    const float4 bias = ((const float4*)b2)[tx];
    const u64 bias01 = packf2(bias.x, bias.y);
    const u64 bias23 = packf2(bias.z, bias.w);

    const float4* h14 = (const float4*)g_h1;
    const int ntiles = EE / BM;

    float4 pf[8];
    int pd = 0;
    int tile = blockIdx.x;

    // prologue: load+stage tile0 into buffer 0, prefetch tile0+G
    if (tile < ntiles) {
        #pragma unroll
        for (int i = 0; i < 8; ++i)
            pf[i] = h14[(size_t)tile * BM * 16 + t + i * TPB];
        if (t < BM)
            pd = m64 ? (int)ei64[(size_t)EE + tile * BM + t]
                     : ei32[(size_t)EE + tile * BM + t];
        float4* d4 = (float4*)AsA;
        #pragma unroll
        for (int i = 0; i < 8; ++i) {
            int s = t + i * TPB;
            float4 v = pf[i];
            v.x = fmaxf(fmaf(v.x, sc4.x, bi4.x), 0.f);
            v.y = fmaxf(fmaf(v.y, sc4.y, bi4.y), 0.f);
            v.z = fmaxf(fmaf(v.z, sc4.z, bi4.z), 0.f);
            v.w = fmaxf(fmaf(v.w, sc4.w, bi4.w), 0.f);
            d4[(s >> 4) * 17 + (s & 15)] = v;
        }
        if (t < BM) {
            cidx0[t] = pd;
            atomicAdd(&g_cnt[pd], 1.0f);
        }
        int nx = tile + G;
        if (nx < ntiles) {
            #pragma unroll
            for (int i = 0; i < 8; ++i)
                pf[i] = h14[(size_t)nx * BM * 16 + t + i * TPB];
            if (t < BM)
                pd = m64 ? (int)ei64[(size_t)EE + nx * BM + t]
                         : ei32[(size_t)EE + nx * BM + t];
        }
    }

    int idx = 0;
    for (; tile < ntiles; tile += G, idx ^= 1) {
        __syncthreads();
        const float4* As4 = (const float4*)(idx ? AsB : AsA);
        const int* cid = idx ? cidx1 : cidx0;

        u64 acc[8][2];
        #pragma unroll
        for (int r = 0; r < 8; ++r) { acc[r][0] = bias01; acc[r][1] = bias23; }
        const ulonglong2* Ws2 = (const ulonglong2*)Ws;
        #pragma unroll
        for (int kk = 0; kk < 16; ++kk) {
            ulonglong2 w0 = Ws2[(4 * kk + 0) * 16 + tx];
            ulonglong2 w1v = Ws2[(4 * kk + 1) * 16 + tx];
            ulonglong2 w2v = Ws2[(4 * kk + 2) * 16 + tx];
            ulonglong2 w3v = Ws2[(4 * kk + 3) * 16 + tx];
            #pragma unroll
            for (int r = 0; r < 8; ++r) {
                float4 av = As4[(ty + 16 * r) * 17 + kk];
                kstep(av, w0, w1v, w2v, w3v, acc[r][0], acc[r][1]);
            }
        }

        // stage tile+G, prefetch tile+2G
        int nx = tile + G;
        if (nx < ntiles) {
            float4* d4 = (float4*)(idx ? AsA : AsB);
            int* ncid = idx ? cidx0 : cidx1;
            #pragma unroll
            for (int i = 0; i < 8; ++i) {
                int s = t + i * TPB;
                float4 v = pf[i];
                v.x = fmaxf(fmaf(v.x, sc4.x, bi4.x), 0.f);
                v.y = fmaxf(fmaf(v.y, sc4.y, bi4.y), 0.f);
                v.z = fmaxf(fmaf(v.z, sc4.z, bi4.z), 0.f);
                v.w = fmaxf(fmaf(v.w, sc4.w, bi4.w), 0.f);
                d4[(s >> 4) * 17 + (s & 15)] = v;
            }
            if (t < BM) {
                ncid[t] = pd;
                atomicAdd(&g_cnt[pd], 1.0f);
            }
            int nx2 = tile + 2 * G;
            if (nx2 < ntiles) {
                #pragma unroll
                for (int i = 0; i < 8; ++i)
                    pf[i] = h14[(size_t)nx2 * BM * 16 + t + i * TPB];
                if (t < BM)
                    pd = m64 ? (int)ei64[(size_t)EE + nx2 * BM + t]
                             : ei32[(size_t)EE + nx2 * BM + t];
            }
        }

        // epilogue: scatter
        #pragma unroll
        for (int r = 0; r < 8; ++r) {
            int m = ty + 16 * r;
            float o0, o1, o2, o3;
            unpackf2(acc[r][0], o0, o1);
            unpackf2(acc[r][1], o2, o3);
            red4(g_agg + (size_t)cid[m] * 64 + tx * 4, o0, o1, o2, o3);
        }
    }
}

// ---------------- node pass 1: o1 = [x||agg/cnt] @ w3 + b3, stats ------------
__global__ void __launch_bounds__(TPB, 2) k_node1(
    const float* __restrict__ x, const float* __restrict__ w3,
    const float* __restrict__ b3)
{
    extern __shared__ float smem[];
    float* As   = smem;                 // BM * BKP
    float* Ws   = As + BM * BKP;        // BKP * 64
    float* ssum = Ws + BKP * 64;        // 64
    float* ssq  = ssum + 64;            // 64
    float* rcnt = ssq + 64;             // BM
    const int t  = threadIdx.x;
    const int tx = t & 15, ty = t >> 4;

    for (int i = t; i < BKP * 64; i += TPB) {
        int k = i >> 6, c = i & 63;
        float v = 0.f;
        if (k < 64)      v = w3[(k + 3) * 64 + c];
        else if (k < 67) v = w3[(k - 64) * 64 + c];
        Ws[i] = v;
    }
    if (t < 64) { ssum[t] = 0.f; ssq[t] = 0.f; }

    const float4 bias = ((const float4*)b3)[tx];
    const u64 bias01 = packf2(bias.x, bias.y);
    const u64 bias23 = packf2(bias.z, bias.w);
    float lsum[4] = {0.f, 0.f, 0.f, 0.f};
    float lsq[4]  = {0.f, 0.f, 0.f, 0.f};

    const float4* agg4 = (const float4*)g_agg;
    float4* As4w = (float4*)As;
    const int ntiles = NPAD / BM;
    for (int tile = blockIdx.x; tile < ntiles; tile += gridDim.x) {
        const int m0 = tile * BM;
        __syncthreads();
        if (t < BM) {
            int m = m0 + t;
            float c = (m < NN) ? g_cnt[m] : 0.f;
            rcnt[t] = 1.f / fmaxf(c, 1.f);
            float* rowp = As + t * BKP + 64;
            if (m < NN) {
                const float* xp = x + (size_t)m * 3;
                rowp[0] = xp[0]; rowp[1] = xp[1]; rowp[2] = xp[2];
            } else { rowp[0] = 0.f; rowp[1] = 0.f; rowp[2] = 0.f; }
            rowp[3] = 0.f;
        }
        __syncthreads();
        #pragma unroll
        for (int i = 0; i < 8; ++i) {
            int s = t + i * TPB;
            int m = s >> 4, q = s & 15;
            int gm = m0 + m;
            float4 v = make_float4(0.f, 0.f, 0.f, 0.f);
            if (gm < NN) v = agg4[(size_t)gm * 16 + q];
            float rc = rcnt[m];
            v.x *= rc; v.y *= rc; v.z *= rc; v.w *= rc;
            As4w[m * 17 + q] = v;
        }
        __syncthreads();

        u64 acc[8][2];
        #pragma unroll
        for (int r = 0; r < 8; ++r) { acc[r][0] = bias01; acc[r][1] = bias23; }
        const float4* As4 = (const float4*)As;
        const ulonglong2* Ws2 = (const ulonglong2*)Ws;
        #pragma unroll
        for (int kk = 0; kk < 17; ++kk) {
            ulonglong2 w0 = Ws2[(4 * kk + 0) * 16 + tx];
            ulonglong2 w1v = Ws2[(4 * kk + 1) * 16 + tx];
            ulonglong2 w2v = Ws2[(4 * kk + 2) * 16 + tx];
            ulonglong2 w3v = Ws2[(4 * kk + 3) * 16 + tx];
            #pragma unroll
            for (int r = 0; r < 8; ++r) {
                float4 av = As4[(ty + 16 * r) * 17 + kk];
                kstep(av, w0, w1v, w2v, w3v, acc[r][0], acc[r][1]);
            }
        }
        float4* o4 = ((float4*)g_o1) + (size_t)m0 * 16;
        #pragma unroll
        for (int r = 0; r < 8; ++r) {
            int m = ty + 16 * r;
            float4 v;
            unpackf2(acc[r][0], v.x, v.y);
            unpackf2(acc[r][1], v.z, v.w);
            o4[m * 16 + tx] = v;
            if (m0 + m < NN) {
                lsum[0] += v.x; lsum[1] += v.y; lsum[2] += v.z; lsum[3] += v.w;
                lsq[0] += v.x * v.x; lsq[1] += v.y * v.y;
                lsq[2] += v.z * v.z; lsq[3] += v.w * v.w;
            }
        }
    }
    __syncthreads();
    #pragma unroll
    for (int c = 0; c < 4; ++c) {
        atomicAdd(&ssum[tx * 4 + c], lsum[c]);
        atomicAdd(&ssq[tx * 4 + c],  lsq[c]);
    }
    __syncthreads();
    if (t < 64) {
        atomicAdd(&g_sum_n[t], (double)ssum[t]);
        atomicAdd(&g_sq_n[t],  (double)ssq[t]);
    }
}

// ---------------- node pass 2: out = relu(bn(o1)) @ w4 + b4 ------------------
__global__ void __launch_bounds__(TPB, 2) k_node2(
    const float* __restrict__ w4, const float* __restrict__ b4,
    const float* __restrict__ g3, const float* __restrict__ be3,
    float* __restrict__ out)
{
    extern __shared__ float smem[];
    float* As = smem;                // BM * BKP (stride 17 f4)
    float* Ws = As + BM * BKP;       // 4096
    float* sc = Ws + 4096;           // 64
    float* bi = sc + 64;             // 64
    const int t  = threadIdx.x;
    const int tx = t & 15, ty = t >> 4;

    for (int i = t; i < 4096; i += TPB) Ws[i] = w4[i];
    if (t < 64) {
        double m = g_sum_n[t] * (1.0 / (double)NN);
        double v = g_sq_n[t] * (1.0 / (double)NN) - m * m;
        double s = (double)g3[t] / sqrt(v + 1e-5);
        sc[t] = (float)s;
        bi[t] = be3[t] - (float)(m * s);
    }
    __syncthreads();
    const float4 sc4 = ((const float4*)sc)[tx];
    const float4 bi4 = ((const float4*)bi)[tx];
    const float4 bias = ((const float4*)b4)[tx];
    const u64 bias01 = packf2(bias.x, bias.y);
    const u64 bias23 = packf2(bias.z, bias.w);

    const float4* o14 = (const float4*)g_o1;
    float4* As4w = (float4*)As;
    float4* out4 = (float4*)out;
    const int ntiles = NPAD / BM;
    for (int tile = blockIdx.x; tile < ntiles; tile += gridDim.x) {
        const int m0 = tile * BM;
        __syncthreads();
        #pragma unroll
        for (int i = 0; i < 8; ++i) {
            int s = t + i * TPB;
            float4 v = o14[(size_t)m0 * 16 + s];
            v.x = fmaxf(fmaf(v.x, sc4.x, bi4.x), 0.f);
            v.y = fmaxf(fmaf(v.y, sc4.y, bi4.y), 0.f);
            v.z = fmaxf(fmaf(v.z, sc4.z, bi4.z), 0.f);
            v.w = fmaxf(fmaf(v.w, sc4.w, bi4.w), 0.f);
            As4w[(s >> 4) * 17 + (s & 15)] = v;
        }
        __syncthreads();

        u64 acc[8][2];
        #pragma unroll
        for (int r = 0; r < 8; ++r) { acc[r][0] = bias01; acc[r][1] = bias23; }
        const float4* As4 = (const float4*)As;
        const ulonglong2* Ws2 = (const ulonglong2*)Ws;
        #pragma unroll
        for (int kk = 0; kk < 16; ++kk) {
            ulonglong2 w0 = Ws2[(4 * kk + 0) * 16 + tx];
            ulonglong2 w1v = Ws2[(4 * kk + 1) * 16 + tx];
            ulonglong2 w2v = Ws2[(4 * kk + 2) * 16 + tx];
            ulonglong2 w3v = Ws2[(4 * kk + 3) * 16 + tx];
            #pragma unroll
            for (int r = 0; r < 8; ++r) {
                float4 av = As4[(ty + 16 * r) * 17 + kk];
                kstep(av, w0, w1v, w2v, w3v, acc[r][0], acc[r][1]);
            }
        }
        #pragma unroll
        for (int r = 0; r < 8; ++r) {
            int m = ty + 16 * r;
            int gm = m0 + m;
            if (gm < NN) {
                float4 v;
                unpackf2(acc[r][0], v.x, v.y);
                unpackf2(acc[r][1], v.z, v.w);
                out4[(size_t)gm * 16 + tx] = v;
            }
        }
    }
}

// ---------------- launch ------------------------------------------------------
extern "C" void kernel_launch(void* const* d_in, const int* in_sizes, int n_in,
                              void* d_out, int out_size) {
    const float* x   = (const float*)d_in[0];
    const void*  ei  = d_in[1];
    const float* ea  = (const float*)d_in[2];
    // d_in[3] = u, d_in[4] = batch  (unused by reference)
    const float* w1  = (const float*)d_in[5];
    const float* b1  = (const float*)d_in[6];
    const float* g1  = (const float*)d_in[7];
    const float* be1 = (const float*)d_in[8];
    const float* w2  = (const float*)d_in[9];
    const float* b2  = (const float*)d_in[10];
    const float* w3  = (const float*)d_in[11];
    const float* b3  = (const float*)d_in[12];
    const float* g3  = (const float*)d_in[13];
    const float* be3 = (const float*)d_in[14];
    const float* w4  = (const float*)d_in[15];
    const float* b4  = (const float*)d_in[16];
    float* out = (float*)d_out;

    const int SM1 = (2 * BM * BKP + BKP * 64 + 128) * 4;             // 87.5 KB
    const int SM2 = (2 * BM * BKP + 4096 + 128) * 4 + 2 * BM * 4;    // 87.5 KB
    const int SM3 = (BM * BKP + BKP * 64 + 128 + BM) * 4;            // k_node1
    const int SM4 = (BM * BKP + 4096 + 128) * 4;                     // k_node2

    cudaFuncSetAttribute(k_edge1, cudaFuncAttributeMaxDynamicSharedMemorySize, SM1);
    cudaFuncSetAttribute(k_edge2, cudaFuncAttributeMaxDynamicSharedMemorySize, SM2);
    cudaFuncSetAttribute(k_node1, cudaFuncAttributeMaxDynamicSharedMemorySize, SM3);
    cudaFuncSetAttribute(k_node2, cudaFuncAttributeMaxDynamicSharedMemorySize, SM4);

    k_init<<<1, TPB>>>(ei);
    k_zero<<<512, TPB>>>();
    k_edge1<<<GRID, TPB, SM1>>>(x, ei, ea, w1, b1);
    k_edge2<<<GRID, TPB, SM2>>>(ei, w2, b2, g1, be1);
    k_node1<<<GRID, TPB, SM3>>>(x, w3, b3);
    k_node2<<<GRID, TPB, SM4>>>(w4, b4, g3, be3, out);
}